// round 1
// baseline (speedup 1.0000x reference)
#include <cuda_runtime.h>

// Problem constants (fixed shapes)
#define K_CODES 1024
#define DIMS    256
#define NTOK    65536           // 4 * 16 * 32 * 32
#define SPATIAL 16384           // 16*32*32 (per-batch spatial size)
#define NZ      (NTOK * DIMS)   // 16777216 z_q elements

// ---------------- scratch (device globals; no allocation allowed) ----------
__device__ float g_embT[DIMS * K_CODES];     // embed transposed [d][k]
__device__ float g_cnorm[K_CODES];           // 0.5 * |e_k|^2
__device__ int   g_idx[NTOK];                // argmin index per token
__device__ float g_counts[K_CODES];          // batch cluster size
__device__ float g_sums[K_CODES * DIMS];     // batch embed sum
__device__ float g_csize[K_CODES];           // Laplace-smoothed cluster size
__device__ float g_newembed[K_CODES * DIMS]; // updated codebook
__device__ float g_sq;                       // sum of squared diffs (loss)

// ---------------- kernel 1: transpose embed, code norms, zero stats --------
__global__ void __launch_bounds__(256) prep_kernel(const float* __restrict__ embed) {
    int k = blockIdx.x;      // code
    int d = threadIdx.x;     // dim
    float v = embed[k * DIMS + d];
    g_embT[d * K_CODES + k] = v;
    g_sums[k * DIMS + d] = 0.f;

    float s = v * v;
    #pragma unroll
    for (int o = 16; o; o >>= 1) s += __shfl_xor_sync(0xffffffffu, s, o);
    __shared__ float red[8];
    if ((d & 31) == 0) red[d >> 5] = s;
    __syncthreads();
    if (d == 0) {
        float t = 0.f;
        #pragma unroll
        for (int i = 0; i < 8; i++) t += red[i];
        g_cnorm[k] = 0.5f * t;
        g_counts[k] = 0.f;
        if (k == 0) g_sq = 0.f;
    }
}

// ---------------- kernel 2: fused GEMM + argmax -----------------------------
// Block: 256 threads (16x16). Tile: 128 tokens x (all 1024 codes in chunks of 128).
// z tile (128 tokens x 256 dims, k-major) cached in smem once per block.
#define GTM 128       // tokens per block
#define GTN 128       // codes per chunk
#define GKB 16        // k-dim step

#define GEMM_SMEM_FLOATS (DIMS * GTM + GKB * GTN + GTN)
#define GEMM_SMEM_BYTES  (GEMM_SMEM_FLOATS * 4)

__global__ void __launch_bounds__(256) gemm_argmax_kernel(const float* __restrict__ z) {
    extern __shared__ float smem[];
    float* zs = smem;                    // [256][128] k-major z tile
    float* bs = smem + DIMS * GTM;       // [GKB][128] embT tile
    float* cn = bs + GKB * GTN;          // [128] code bias

    const int tid = threadIdx.x;
    const int t0  = blockIdx.x * GTM;
    const int b   = t0 >> 14;
    const int s0  = t0 & (SPATIAL - 1);
    const float* zb = z + (size_t)b * DIMS * SPATIAL + s0;

    // load z tile: 256 k-rows x 128 floats (coalesced float4)
    #pragma unroll 4
    for (int i = tid; i < DIMS * (GTM / 4); i += 256) {
        int k  = i >> 5;        // / 32
        int m4 = i & 31;
        float4 v = *(const float4*)(zb + (size_t)k * SPATIAL + m4 * 4);
        *(float4*)(&zs[k * GTM + m4 * 4]) = v;
    }
    __syncthreads();

    const int ty = tid >> 4;
    const int tx = tid & 15;

    float best[8];
    int   bidx[8];
    #pragma unroll
    for (int i = 0; i < 8; i++) { best[i] = -3.0e38f; bidx[i] = 0; }

    for (int n0 = 0; n0 < K_CODES; n0 += GTN) {
        __syncthreads();   // protect cn/bs from previous chunk's readers
        if (tid < GTN) cn[tid] = g_cnorm[n0 + tid];

        float acc[8][8];
        #pragma unroll
        for (int i = 0; i < 8; i++)
            #pragma unroll
            for (int j = 0; j < 8; j++) acc[i][j] = 0.f;

        for (int kk = 0; kk < DIMS; kk += GKB) {
            __syncthreads();
            // load embT tile [GKB][128], coalesced float4
            #pragma unroll
            for (int i = tid; i < GKB * (GTN / 4); i += 256) {
                int k  = i >> 5;
                int n4 = i & 31;
                *(float4*)&bs[k * GTN + n4 * 4] =
                    *(const float4*)(g_embT + (size_t)(kk + k) * K_CODES + n0 + n4 * 4);
            }
            __syncthreads();

            #pragma unroll
            for (int k = 0; k < GKB; k++) {
                float rm[8], rn[8];
                *(float4*)&rm[0] = *(float4*)&zs[(kk + k) * GTM + ty * 8];
                *(float4*)&rm[4] = *(float4*)&zs[(kk + k) * GTM + ty * 8 + 4];
                *(float4*)&rn[0] = *(float4*)&bs[k * GTN + tx * 8];
                *(float4*)&rn[4] = *(float4*)&bs[k * GTN + tx * 8 + 4];
                #pragma unroll
                for (int i = 0; i < 8; i++)
                    #pragma unroll
                    for (int j = 0; j < 8; j++)
                        acc[i][j] += rm[i] * rn[j];
            }
        }

        // epilogue: score = dot - 0.5|e|^2 ; argmax with lowest-index tiebreak
        #pragma unroll
        for (int i = 0; i < 8; i++) {
            float v = -3.0e38f;
            int   ji = 0;
            #pragma unroll
            for (int j = 0; j < 8; j++) {
                float s = acc[i][j] - cn[tx * 8 + j];
                if (s > v) { v = s; ji = n0 + tx * 8 + j; }
            }
            // reduce across the 16 tx lanes (stays within 16-lane groups)
            #pragma unroll
            for (int o = 8; o >= 1; o >>= 1) {
                float ov = __shfl_xor_sync(0xffffffffu, v, o);
                int   oj = __shfl_xor_sync(0xffffffffu, ji, o);
                if (ov > v || (ov == v && oj < ji)) { v = ov; ji = oj; }
            }
            if (v > best[i] || (v == best[i] && ji < bidx[i])) { best[i] = v; bidx[i] = ji; }
        }
    }

    if (tx == 0) {
        #pragma unroll
        for (int i = 0; i < 8; i++)
            g_idx[t0 + ty * 8 + i] = bidx[i];
    }
}

// ---------------- kernel 3: segment-sum scatter (atomics) -------------------
__global__ void __launch_bounds__(256) scatter_kernel(const float* __restrict__ z) {
    int t = blockIdx.x * 256 + threadIdx.x;
    int b = t >> 14;
    int s = t & (SPATIAL - 1);
    int kk = g_idx[t];
    const float* zp = z + (size_t)b * DIMS * SPATIAL + s;
    float* sm = g_sums + (size_t)kk * DIMS;
    atomicAdd(&g_counts[kk], 1.f);
    #pragma unroll 4
    for (int c = 0; c < DIMS; c++)
        atomicAdd(&sm[c], zp[(size_t)c * SPATIAL]);
}

// ---------------- kernel 4: EMA cluster size + Laplace smoothing ------------
__global__ void __launch_bounds__(1024) csize_kernel(const float* __restrict__ ema_cs) {
    int k = threadIdx.x;
    float cs = 0.99f * ema_cs[k] + 0.01f * g_counts[k];
    __shared__ float red[32];
    float s = cs;
    #pragma unroll
    for (int o = 16; o; o >>= 1) s += __shfl_xor_sync(0xffffffffu, s, o);
    if ((k & 31) == 0) red[k >> 5] = s;
    __syncthreads();
    if (k < 32) {
        float t = red[k];
        #pragma unroll
        for (int o = 16; o; o >>= 1) t += __shfl_xor_sync(0xffffffffu, t, o);
        if (k == 0) red[0] = t;
    }
    __syncthreads();
    float n = red[0];
    g_csize[k] = (cs + 1e-5f) / (n + K_CODES * 1e-5f) * n;
}

// ---------------- kernel 5: updated codebook --------------------------------
__global__ void __launch_bounds__(256) newembed_kernel(const float* __restrict__ ema_es) {
    int k = blockIdx.x, d = threadIdx.x;
    size_t o = (size_t)k * DIMS + d;
    g_newembed[o] = (0.99f * ema_es[o] + 0.01f * g_sums[o]) / g_csize[k];
}

// ---------------- kernel 6: gather z_q, loss partial, indices ---------------
__global__ void __launch_bounds__(256) gather_kernel(const float* __restrict__ z,
                                                     float* __restrict__ out) {
    int t = blockIdx.x * 256 + threadIdx.x;
    int b = t >> 14;
    int s = t & (SPATIAL - 1);
    int kk = g_idx[t];
    const float* zp = z + (size_t)b * DIMS * SPATIAL + s;
    float*       op = out + (size_t)b * DIMS * SPATIAL + s;
    const float* er = g_newembed + (size_t)kk * DIMS;

    float acc = 0.f;
    #pragma unroll 4
    for (int c = 0; c < DIMS; c++) {
        float zv = zp[(size_t)c * SPATIAL];
        float e  = __ldg(&er[c]);
        float d2 = zv - e;
        acc += d2 * d2;
        op[(size_t)c * SPATIAL] = zv + (e - zv);   // straight-through (matches ref fp path)
    }
    out[(size_t)NZ + 1 + t] = (float)kk;           // indices output (cast to float)

    #pragma unroll
    for (int o = 16; o; o >>= 1) acc += __shfl_xor_sync(0xffffffffu, acc, o);
    __shared__ float red[8];
    if ((threadIdx.x & 31) == 0) red[threadIdx.x >> 5] = acc;
    __syncthreads();
    if (threadIdx.x == 0) {
        float tt = 0.f;
        #pragma unroll
        for (int i = 0; i < 8; i++) tt += red[i];
        atomicAdd(&g_sq, tt);
    }
}

// ---------------- kernel 7: final loss ---------------------------------------
__global__ void loss_kernel(float* __restrict__ out) {
    out[NZ] = 0.25f * g_sq / (float)NZ;
}

// ---------------- launch -----------------------------------------------------
extern "C" void kernel_launch(void* const* d_in, const int* in_sizes, int n_in,
                              void* d_out, int out_size) {
    const float* z       = (const float*)d_in[0];
    const float* embed   = (const float*)d_in[1];
    const float* ema_cs  = (const float*)d_in[2];
    const float* ema_es  = (const float*)d_in[3];
    float* out = (float*)d_out;

    cudaFuncSetAttribute(gemm_argmax_kernel,
                         cudaFuncAttributeMaxDynamicSharedMemorySize, GEMM_SMEM_BYTES);

    prep_kernel<<<K_CODES, 256>>>(embed);
    gemm_argmax_kernel<<<NTOK / GTM, 256, GEMM_SMEM_BYTES>>>(z);
    scatter_kernel<<<NTOK / 256, 256>>>(z);
    csize_kernel<<<1, 1024>>>(ema_cs);
    newembed_kernel<<<K_CODES, 256>>>(ema_es);
    gather_kernel<<<NTOK / 256, 256>>>(z, out);
    loss_kernel<<<1, 1>>>(out);
}

// round 3
// speedup vs baseline: 1.9394x; 1.9394x over previous
#include <cuda_runtime.h>
#include <cuda_bf16.h>
#include <cstdint>

// Problem constants (fixed shapes)
#define K_CODES 1024
#define DIMS    256
#define NTOK    65536           // 4 * 16 * 32 * 32
#define SPATIAL 16384           // 16*32*32
#define NZ      (NTOK * DIMS)

// A = [tok][ z_hi(256) | z_lo(256) ]  (token-major bf16)
// B = [code][ e_hi(256) | e_lo(256) | e_hi(256) ]  (K logical = 768)
#define AW      512
#define BW      768

// ---------------- scratch (device globals) ----------------------------------
__device__ __align__(256) __nv_bfloat16 g_A[(size_t)NTOK * AW];     // 64 MB
__device__ __align__(256) __nv_bfloat16 g_B[(size_t)K_CODES * BW];  // 1.5 MB
__device__ float g_cnorm[K_CODES];           // 0.5 * |e_k|^2
__device__ int   g_idx[NTOK];
__device__ float g_counts[K_CODES];
__device__ float g_sums[K_CODES * DIMS];
__device__ float g_csize[K_CODES];
__device__ float g_newembed[K_CODES * DIMS];
__device__ float g_sq;

// ---------------- helpers ----------------------------------------------------
__device__ __forceinline__ uint32_t smem_u32(const void* p) {
    uint32_t a;
    asm("{ .reg .u64 t; cvta.to.shared.u64 t, %1; cvt.u32.u64 %0, t; }" : "=r"(a) : "l"(p));
    return a;
}

__device__ __forceinline__ void ldsm4(uint32_t (&r)[4], uint32_t addr) {
    asm volatile("ldmatrix.sync.aligned.m8n8.x4.shared.b16 {%0,%1,%2,%3}, [%4];"
                 : "=r"(r[0]), "=r"(r[1]), "=r"(r[2]), "=r"(r[3]) : "r"(addr));
}

__device__ __forceinline__ void mma16816(float (&d)[4], const uint32_t (&a)[4],
                                         uint32_t b0, uint32_t b1) {
    asm volatile("mma.sync.aligned.m16n8k16.row.col.f32.bf16.bf16.f32 "
                 "{%0,%1,%2,%3},{%4,%5,%6,%7},{%8,%9},{%0,%1,%2,%3};"
                 : "+f"(d[0]), "+f"(d[1]), "+f"(d[2]), "+f"(d[3])
                 : "r"(a[0]), "r"(a[1]), "r"(a[2]), "r"(a[3]), "r"(b0), "r"(b1));
}

// ---------------- kernel 1a: embed -> bf16 split + code norms ---------------
__global__ void __launch_bounds__(256) prep_embed_kernel(const float* __restrict__ embed) {
    int k = blockIdx.x, d = threadIdx.x;
    float e = embed[k * DIMS + d];
    __nv_bfloat16 hi = __float2bfloat16(e);
    __nv_bfloat16 lo = __float2bfloat16(e - __bfloat162float(hi));
    g_B[(size_t)k * BW + d]       = hi;
    g_B[(size_t)k * BW + 256 + d] = lo;
    g_B[(size_t)k * BW + 512 + d] = hi;
    g_sums[k * DIMS + d] = 0.f;

    float s = e * e;
    #pragma unroll
    for (int o = 16; o; o >>= 1) s += __shfl_xor_sync(0xffffffffu, s, o);
    __shared__ float red[8];
    if ((d & 31) == 0) red[d >> 5] = s;
    __syncthreads();
    if (d == 0) {
        float t = 0.f;
        #pragma unroll
        for (int i = 0; i < 8; i++) t += red[i];
        g_cnorm[k] = 0.5f * t;
        g_counts[k] = 0.f;
        if (k == 0) g_sq = 0.f;
    }
}

// ---------------- kernel 1b: z transpose + bf16 split ------------------------
__global__ void __launch_bounds__(256) prep_z_kernel(const float* __restrict__ z) {
    __shared__ float tile[256 * 33];
    int tid = threadIdx.x;
    int t0 = blockIdx.x * 32;
    int b = t0 >> 14, s0 = t0 & (SPATIAL - 1);
    const float* zp = z + (size_t)b * DIMS * SPATIAL + s0;

    for (int i = tid; i < 256 * 32; i += 256) {
        int c = i >> 5, s = i & 31;
        tile[c * 33 + s] = zp[(size_t)c * SPATIAL + s];
    }
    __syncthreads();

    for (int i = tid; i < 32 * 128; i += 256) {
        int r = i >> 7, c2 = (i & 127) * 2;
        float v0 = tile[c2 * 33 + r], v1 = tile[(c2 + 1) * 33 + r];
        __nv_bfloat16 h0 = __float2bfloat16(v0), h1 = __float2bfloat16(v1);
        __nv_bfloat162 hh; hh.x = h0; hh.y = h1;
        __nv_bfloat162 ll;
        ll.x = __float2bfloat16(v0 - __bfloat162float(h0));
        ll.y = __float2bfloat16(v1 - __bfloat162float(h1));
        size_t base = (size_t)(t0 + r) * AW;
        *(__nv_bfloat162*)&g_A[base + c2]       = hh;
        *(__nv_bfloat162*)&g_A[base + 256 + c2] = ll;
    }
}

// ---------------- kernel 2: mma.sync GEMM + argmax ---------------------------
// CTA: 128 tokens x 1024 codes (4 n-chunks of 256). 8 warps = 2(M) x 4(N),
// warp tile 64x64. K logical 768 in 24 chunks of 32 (double-buffered B).
#define APITCH_B 1040          // 520 bf16  (bank stride 4 words, 16B-aligned)
#define BPITCH_B 80            // 40 bf16   (bank stride 20 words, 16B-aligned)
#define SM_A   0               // 128 * 1040 = 133120
#define SM_B   133120          // 2 * 20480
#define BBUF   20480
#define SM_EB  174080          // float[128][4]
#define SM_EI  176128          // int[128][4]
#define GEMM_SMEM 178176

__global__ void __launch_bounds__(256, 1) mma_argmax_kernel() {
    extern __shared__ char smem[];
    const uint32_t sb = smem_u32(smem);
    const int tid  = threadIdx.x;
    const int lane = tid & 31;
    const int warp = tid >> 5;
    const int wm = warp >> 2, wn = warp & 3;
    const int t0 = blockIdx.x * 128;

    // load A tile: 128 rows x 64 int4 (coalesced LDG, conflict-free STS)
    {
        const int4* gA = (const int4*)(g_A + (size_t)t0 * AW);
        #pragma unroll
        for (int i = 0; i < 32; i++) {
            int idx = tid + i * 256;
            int row = idx >> 6, u = idx & 63;
            int4 v = gA[row * 64 + u];
            *(int4*)(smem + SM_A + row * APITCH_B + u * 16) = v;
        }
    }

    float best[8];
    int   bidx[8];
    #pragma unroll
    for (int i = 0; i < 8; i++) { best[i] = -3.0e38f; bidx[i] = 0; }

    const int g  = lane >> 2;
    const int tq = lane & 3;
    const int a_row  = lane & 15;
    const int a_colq = (lane >> 4) << 3;
    const int b_rowl = (lane & 7) + ((lane & 16) ? 8 : 0);
    const int b_coll = (lane & 8) ? 8 : 0;

    __syncthreads();

    for (int nc = 0; nc < 4; nc++) {
        const int n0 = nc * 256;
        float acc[4][8][4];
        #pragma unroll
        for (int mt = 0; mt < 4; mt++)
            #pragma unroll
            for (int nt = 0; nt < 8; nt++)
                #pragma unroll
                for (int q = 0; q < 4; q++) acc[mt][nt][q] = 0.f;

        // prefetch B chunk 0 (256 rows x 32 bf16)
        int4 pre[4];
        #pragma unroll
        for (int j = 0; j < 4; j++) {
            int idx = tid + j * 256;
            int row = idx >> 2, u = idx & 3;
            pre[j] = *(const int4*)(g_B + (size_t)(n0 + row) * BW + u * 8);
        }

        for (int c = 0; c < 24; c++) {
            const uint32_t bbase = sb + SM_B + (c & 1) * BBUF;
            #pragma unroll
            for (int j = 0; j < 4; j++) {
                int idx = tid + j * 256;
                int row = idx >> 2, u = idx & 3;
                *(int4*)(smem + SM_B + (c & 1) * BBUF + row * BPITCH_B + u * 16) = pre[j];
            }
            __syncthreads();
            if (c < 23) {
                const int kb = (c + 1) * 32;
                #pragma unroll
                for (int j = 0; j < 4; j++) {
                    int idx = tid + j * 256;
                    int row = idx >> 2, u = idx & 3;
                    pre[j] = *(const int4*)(g_B + (size_t)(n0 + row) * BW + kb + u * 8);
                }
            }
            // logical k 32c..32c+31 -> A physical col (hi region duplicated)
            const int aphys = (c < 8) ? c * 32 : c * 32 - 256;
            #pragma unroll
            for (int k16 = 0; k16 < 2; k16++) {
                const int acol = aphys + k16 * 16;
                uint32_t afr[4][4];
                #pragma unroll
                for (int mt = 0; mt < 4; mt++) {
                    uint32_t ad = sb + SM_A + (wm * 64 + mt * 16 + a_row) * APITCH_B
                                + (acol + a_colq) * 2;
                    ldsm4(afr[mt], ad);
                }
                #pragma unroll
                for (int bt = 0; bt < 4; bt++) {
                    uint32_t bfr[4];
                    uint32_t bd = bbase + (wn * 64 + bt * 16 + b_rowl) * BPITCH_B
                                + (k16 * 16 + b_coll) * 2;
                    ldsm4(bfr, bd);
                    #pragma unroll
                    for (int mt = 0; mt < 4; mt++) {
                        mma16816(acc[mt][2 * bt],     afr[mt], bfr[0], bfr[1]);
                        mma16816(acc[mt][2 * bt + 1], afr[mt], bfr[2], bfr[3]);
                    }
                }
            }
        }

        // epilogue: subtract 0.5|e|^2, update running per-row argmax
        #pragma unroll
        for (int mt = 0; mt < 4; mt++) {
            #pragma unroll
            for (int half = 0; half < 2; half++) {
                const int slot = mt * 2 + half;
                float v = best[slot];
                int   vi = bidx[slot];
                #pragma unroll
                for (int nt = 0; nt < 8; nt++) {
                    int code = n0 + wn * 64 + nt * 8 + tq * 2;
                    float s0 = acc[mt][nt][half * 2 + 0] - __ldg(&g_cnorm[code]);
                    float s1 = acc[mt][nt][half * 2 + 1] - __ldg(&g_cnorm[code + 1]);
                    if (s0 > v) { v = s0; vi = code; }
                    if (s1 > v) { v = s1; vi = code + 1; }
                }
                best[slot] = v; bidx[slot] = vi;
            }
        }
    }

    // reduce across the 4 lanes of each quad (columns), then across wn warps
    #pragma unroll
    for (int slot = 0; slot < 8; slot++) {
        float v = best[slot];
        int   vi = bidx[slot];
        #pragma unroll
        for (int off = 1; off <= 2; off <<= 1) {
            float ov = __shfl_xor_sync(0xffffffffu, v, off);
            int   oi = __shfl_xor_sync(0xffffffffu, vi, off);
            if (ov > v || (ov == v && oi < vi)) { v = ov; vi = oi; }
        }
        if (tq == 0) {
            int mt = slot >> 1, half = slot & 1;
            int row = wm * 64 + mt * 16 + half * 8 + g;
            *(float*)(smem + SM_EB + (row * 4 + wn) * 4) = v;
            *(int*)(smem + SM_EI + (row * 4 + wn) * 4)   = vi;
        }
    }
    __syncthreads();
    if (tid < 128) {
        float v = -3.0e38f;
        int   vi = 0;
        #pragma unroll
        for (int w = 0; w < 4; w++) {
            float ov = *(float*)(smem + SM_EB + (tid * 4 + w) * 4);
            int   oi = *(int*)(smem + SM_EI + (tid * 4 + w) * 4);
            if (ov > v || (ov == v && oi < vi)) { v = ov; vi = oi; }
        }
        g_idx[t0 + tid] = vi;
    }
}

// ---------------- kernel 3: segment-sum scatter ------------------------------
__global__ void __launch_bounds__(256) scatter_kernel(const float* __restrict__ z) {
    int t = blockIdx.x * 256 + threadIdx.x;
    int b = t >> 14;
    int s = t & (SPATIAL - 1);
    int kk = g_idx[t];
    const float* zp = z + (size_t)b * DIMS * SPATIAL + s;
    float* sm = g_sums + (size_t)kk * DIMS;
    atomicAdd(&g_counts[kk], 1.f);
    #pragma unroll 4
    for (int c = 0; c < DIMS; c++)
        atomicAdd(&sm[c], zp[(size_t)c * SPATIAL]);
}

// ---------------- kernel 4: EMA cluster size + Laplace smoothing -------------
__global__ void __launch_bounds__(1024) csize_kernel(const float* __restrict__ ema_cs) {
    int k = threadIdx.x;
    float cs = 0.99f * ema_cs[k] + 0.01f * g_counts[k];
    __shared__ float red[32];
    float s = cs;
    #pragma unroll
    for (int o = 16; o; o >>= 1) s += __shfl_xor_sync(0xffffffffu, s, o);
    if ((k & 31) == 0) red[k >> 5] = s;
    __syncthreads();
    if (k < 32) {
        float t = red[k];
        #pragma unroll
        for (int o = 16; o; o >>= 1) t += __shfl_xor_sync(0xffffffffu, t, o);
        if (k == 0) red[0] = t;
    }
    __syncthreads();
    float n = red[0];
    g_csize[k] = (cs + 1e-5f) / (n + K_CODES * 1e-5f) * n;
}

// ---------------- kernel 5: updated codebook ---------------------------------
__global__ void __launch_bounds__(256) newembed_kernel(const float* __restrict__ ema_es) {
    int k = blockIdx.x, d = threadIdx.x;
    size_t o = (size_t)k * DIMS + d;
    g_newembed[o] = (0.99f * ema_es[o] + 0.01f * g_sums[o]) / g_csize[k];
}

// ---------------- kernel 6: gather z_q, loss partial, indices ----------------
__global__ void __launch_bounds__(256) gather_kernel(const float* __restrict__ z,
                                                     float* __restrict__ out) {
    int t = blockIdx.x * 256 + threadIdx.x;
    int b = t >> 14;
    int s = t & (SPATIAL - 1);
    int kk = g_idx[t];
    const float* zp = z + (size_t)b * DIMS * SPATIAL + s;
    float*       op = out + (size_t)b * DIMS * SPATIAL + s;
    const float* er = g_newembed + (size_t)kk * DIMS;

    float acc = 0.f;
    #pragma unroll 4
    for (int c = 0; c < DIMS; c++) {
        float zv = zp[(size_t)c * SPATIAL];
        float e  = __ldg(&er[c]);
        float d2 = zv - e;
        acc += d2 * d2;
        op[(size_t)c * SPATIAL] = zv + (e - zv);
    }
    out[(size_t)NZ + 1 + t] = (float)kk;

    #pragma unroll
    for (int o = 16; o; o >>= 1) acc += __shfl_xor_sync(0xffffffffu, acc, o);
    __shared__ float red[8];
    if ((threadIdx.x & 31) == 0) red[threadIdx.x >> 5] = acc;
    __syncthreads();
    if (threadIdx.x == 0) {
        float tt = 0.f;
        #pragma unroll
        for (int i = 0; i < 8; i++) tt += red[i];
        atomicAdd(&g_sq, tt);
    }
}

// ---------------- kernel 7: final loss ---------------------------------------
__global__ void loss_kernel(float* __restrict__ out) {
    out[NZ] = 0.25f * g_sq / (float)NZ;
}

// ---------------- launch -----------------------------------------------------
extern "C" void kernel_launch(void* const* d_in, const int* in_sizes, int n_in,
                              void* d_out, int out_size) {
    (void)in_sizes; (void)n_in; (void)out_size;
    const float* z      = (const float*)d_in[0];
    const float* embed  = (const float*)d_in[1];
    const float* ema_cs = (const float*)d_in[2];
    const float* ema_es = (const float*)d_in[3];
    float* out = (float*)d_out;

    static int smem_set = 0;
    if (!smem_set) {
        cudaFuncSetAttribute(mma_argmax_kernel,
                             cudaFuncAttributeMaxDynamicSharedMemorySize, GEMM_SMEM);
        smem_set = 1;
    }

    prep_embed_kernel<<<K_CODES, 256>>>(embed);
    prep_z_kernel<<<NTOK / 32, 256>>>(z);
    mma_argmax_kernel<<<NTOK / 128, 256, GEMM_SMEM>>>();
    scatter_kernel<<<NTOK / 256, 256>>>(z);
    csize_kernel<<<1, 1024>>>(ema_cs);
    newembed_kernel<<<K_CODES, 256>>>(ema_es);
    gather_kernel<<<NTOK / 256, 256>>>(z, out);
    loss_kernel<<<1, 1>>>(out);
}

// round 6
// speedup vs baseline: 2.0891x; 1.0772x over previous
#include <cuda_runtime.h>
#include <cuda_bf16.h>
#include <cstdint>

// Problem constants (fixed shapes)
#define K_CODES 1024
#define DIMS    256
#define NTOK    65536           // 4 * 16 * 32 * 32
#define SPATIAL 16384           // 16*32*32
#define NZ      (NTOK * DIMS)

// A = [tok][ z_hi(256) | z_lo(256) ]  (token-major bf16)
// B = [code][ e_hi(256) | e_lo(256) | e_hi(256) ]  (K logical = 768)
#define AW      512
#define BW      768

// ---------------- scratch (device globals) ----------------------------------
__device__ __align__(256) __nv_bfloat16 g_A[(size_t)NTOK * AW];     // 64 MB
__device__ __align__(256) float         g_Zt[(size_t)NTOK * DIMS];  // 64 MB fp32 token-major
__device__ __align__(256) __nv_bfloat16 g_B[(size_t)K_CODES * BW];  // 1.5 MB
__device__ float g_cnorm[K_CODES];           // 0.5 * |e_k|^2
__device__ int   g_idx[NTOK];
__device__ int   g_cnt[K_CODES];
__device__ int   g_segstart[K_CODES];
__device__ int   g_cursor[K_CODES];
__device__ int   g_sorted[NTOK];
__device__ float g_csize[K_CODES];
__device__ float g_newembed[K_CODES * DIMS];
__device__ float g_sq;

// ---------------- helpers ----------------------------------------------------
__device__ __forceinline__ uint32_t smem_u32(const void* p) {
    uint32_t a;
    asm("{ .reg .u64 t; cvta.to.shared.u64 t, %1; cvt.u32.u64 %0, t; }" : "=r"(a) : "l"(p));
    return a;
}

__device__ __forceinline__ void ldsm4(uint32_t (&r)[4], uint32_t addr) {
    asm volatile("ldmatrix.sync.aligned.m8n8.x4.shared.b16 {%0,%1,%2,%3}, [%4];"
                 : "=r"(r[0]), "=r"(r[1]), "=r"(r[2]), "=r"(r[3]) : "r"(addr));
}

__device__ __forceinline__ void mma16816(float (&d)[4], const uint32_t (&a)[4],
                                         uint32_t b0, uint32_t b1) {
    asm volatile("mma.sync.aligned.m16n8k16.row.col.f32.bf16.bf16.f32 "
                 "{%0,%1,%2,%3},{%4,%5,%6,%7},{%8,%9},{%0,%1,%2,%3};"
                 : "+f"(d[0]), "+f"(d[1]), "+f"(d[2]), "+f"(d[3])
                 : "r"(a[0]), "r"(a[1]), "r"(a[2]), "r"(a[3]), "r"(b0), "r"(b1));
}

__device__ __forceinline__ void cp16(uint32_t saddr, const void* gaddr) {
    asm volatile("cp.async.cg.shared.global [%0], [%1], 16;" :: "r"(saddr), "l"(gaddr));
}
#define CP_COMMIT() asm volatile("cp.async.commit_group;")

// ---------------- kernel 1a: embed -> bf16 split + code norms ---------------
__global__ void __launch_bounds__(256) prep_embed_kernel(const float* __restrict__ embed) {
    int k = blockIdx.x, d = threadIdx.x;
    float e = embed[k * DIMS + d];
    __nv_bfloat16 hi = __float2bfloat16(e);
    __nv_bfloat16 lo = __float2bfloat16(e - __bfloat162float(hi));
    g_B[(size_t)k * BW + d]       = hi;
    g_B[(size_t)k * BW + 256 + d] = lo;
    g_B[(size_t)k * BW + 512 + d] = hi;

    float s = e * e;
    #pragma unroll
    for (int o = 16; o; o >>= 1) s += __shfl_xor_sync(0xffffffffu, s, o);
    __shared__ float red[8];
    if ((d & 31) == 0) red[d >> 5] = s;
    __syncthreads();
    if (d == 0) {
        float t = 0.f;
        #pragma unroll
        for (int i = 0; i < 8; i++) t += red[i];
        g_cnorm[k] = 0.5f * t;
        g_cnt[k] = 0;
        if (k == 0) g_sq = 0.f;
    }
}

// ---------------- kernel 1b: z transpose + bf16 split + fp32 copy ------------
__global__ void __launch_bounds__(256) prep_z_kernel(const float* __restrict__ z) {
    __shared__ float tile[256 * 33];
    int tid = threadIdx.x;
    int t0 = blockIdx.x * 32;
    int b = t0 >> 14, s0 = t0 & (SPATIAL - 1);
    const float* zp = z + (size_t)b * DIMS * SPATIAL + s0;

    for (int i = tid; i < 256 * 32; i += 256) {
        int c = i >> 5, s = i & 31;
        tile[c * 33 + s] = zp[(size_t)c * SPATIAL + s];
    }
    __syncthreads();

    for (int i = tid; i < 32 * 128; i += 256) {
        int r = i >> 7, c2 = (i & 127) * 2;
        float v0 = tile[c2 * 33 + r], v1 = tile[(c2 + 1) * 33 + r];
        __nv_bfloat16 h0 = __float2bfloat16(v0), h1 = __float2bfloat16(v1);
        __nv_bfloat162 hh; hh.x = h0; hh.y = h1;
        __nv_bfloat162 ll;
        ll.x = __float2bfloat16(v0 - __bfloat162float(h0));
        ll.y = __float2bfloat16(v1 - __bfloat162float(h1));
        size_t base = (size_t)(t0 + r) * AW;
        *(__nv_bfloat162*)&g_A[base + c2]       = hh;
        *(__nv_bfloat162*)&g_A[base + 256 + c2] = ll;
        float2 f2; f2.x = v0; f2.y = v1;
        *(float2*)&g_Zt[(size_t)(t0 + r) * DIMS + c2] = f2;
    }
}

// ---------------- kernel 2: mma.sync GEMM + argmax (cp.async pipelined) ------
// CTA: 128 tokens x 1024 codes (4 n-chunks of 256). 8 warps = 2(M) x 4(N),
// warp tile 64x64. K logical 768 in 24 chunks of 32, 4-stage cp.async on B.
#define APITCH_B 1040          // 520 bf16
#define BPITCH_B 80            // 40 bf16
#define SM_A   0               // 128 * 1040 = 133120
#define SM_B   133120
#define BBUF   20480           // one stage: 256 rows x 80 B
#define SM_EB  (SM_B + 4 * BBUF)     // 215040
#define SM_EI  (SM_EB + 2048)        // 217088
#define GEMM_SMEM (SM_EI + 2048)     // 219136

__device__ __forceinline__ void issue_b(uint32_t sb, int stage, int n0, int c, int tid) {
    const __nv_bfloat16* gp = g_B + c * 32;
    uint32_t base = sb + SM_B + stage * BBUF;
    // 256 rows x 32 bf16 = 1024 x 16B transfers = 4 iterations of 256 threads
    #pragma unroll
    for (int j = 0; j < 4; j++) {
        int idx = tid + j * 256;
        int row = idx >> 2, u = idx & 3;
        cp16(base + row * BPITCH_B + u * 16, gp + (size_t)(n0 + row) * BW + u * 8);
    }
    CP_COMMIT();
}

__global__ void __launch_bounds__(256, 1) mma_argmax_kernel() {
    extern __shared__ char smem[];
    const uint32_t sb = smem_u32(smem);
    const int tid  = threadIdx.x;
    const int lane = tid & 31;
    const int warp = tid >> 5;
    const int wm = warp >> 2, wn = warp & 3;
    const int t0 = blockIdx.x * 128;

    // load A tile: 128 rows x 64 int4 (coalesced LDG, conflict-free STS)
    {
        const int4* gA = (const int4*)(g_A + (size_t)t0 * AW);
        #pragma unroll
        for (int i = 0; i < 32; i++) {
            int idx = tid + i * 256;
            int row = idx >> 6, u = idx & 63;
            int4 v = gA[row * 64 + u];
            *(int4*)(smem + SM_A + row * APITCH_B + u * 16) = v;
        }
    }

    float best[8];
    int   bidx[8];
    #pragma unroll
    for (int i = 0; i < 8; i++) { best[i] = -3.0e38f; bidx[i] = 0; }

    const int g  = lane >> 2;
    const int tq = lane & 3;
    const int a_row  = lane & 15;
    const int a_colq = (lane >> 4) << 3;
    const int b_rowl = (lane & 7) + ((lane & 16) ? 8 : 0);
    const int b_coll = (lane & 8) ? 8 : 0;

    __syncthreads();

    for (int nc = 0; nc < 4; nc++) {
        const int n0 = nc * 256;
        float acc[4][8][4];
        #pragma unroll
        for (int mt = 0; mt < 4; mt++)
            #pragma unroll
            for (int nt = 0; nt < 8; nt++)
                #pragma unroll
                for (int q = 0; q < 4; q++) acc[mt][nt][q] = 0.f;

        // prologue: stages 0..2
        issue_b(sb, 0, n0, 0, tid);
        issue_b(sb, 1, n0, 1, tid);
        issue_b(sb, 2, n0, 2, tid);

        for (int c = 0; c < 24; c++) {
            // chunk c guaranteed complete when <= (groups committed after c) outstanding
            int rem = 23 - c;
            if (rem >= 2)      asm volatile("cp.async.wait_group 2;");
            else if (rem == 1) asm volatile("cp.async.wait_group 1;");
            else               asm volatile("cp.async.wait_group 0;");
            __syncthreads();
            if (c + 3 < 24) issue_b(sb, (c + 3) & 3, n0, c + 3, tid);

            const uint32_t bbase = sb + SM_B + (c & 3) * BBUF;
            // logical k 32c..32c+31 -> A physical col (hi region duplicated)
            const int aphys = (c < 8) ? c * 32 : c * 32 - 256;
            #pragma unroll
            for (int k16 = 0; k16 < 2; k16++) {
                const int acol = aphys + k16 * 16;
                uint32_t afr[4][4];
                #pragma unroll
                for (int mt = 0; mt < 4; mt++) {
                    uint32_t ad = sb + SM_A + (wm * 64 + mt * 16 + a_row) * APITCH_B
                                + (acol + a_colq) * 2;
                    ldsm4(afr[mt], ad);
                }
                #pragma unroll
                for (int bt = 0; bt < 4; bt++) {
                    uint32_t bfr[4];
                    uint32_t bd = bbase + (wn * 64 + bt * 16 + b_rowl) * BPITCH_B
                                + (k16 * 16 + b_coll) * 2;
                    ldsm4(bfr, bd);
                    #pragma unroll
                    for (int mt = 0; mt < 4; mt++) {
                        mma16816(acc[mt][2 * bt],     afr[mt], bfr[0], bfr[1]);
                        mma16816(acc[mt][2 * bt + 1], afr[mt], bfr[2], bfr[3]);
                    }
                }
            }
        }

        // epilogue: subtract 0.5|e|^2, update running per-row argmax
        #pragma unroll
        for (int mt = 0; mt < 4; mt++) {
            #pragma unroll
            for (int half = 0; half < 2; half++) {
                const int slot = mt * 2 + half;
                float v = best[slot];
                int   vi = bidx[slot];
                #pragma unroll
                for (int nt = 0; nt < 8; nt++) {
                    int code = n0 + wn * 64 + nt * 8 + tq * 2;
                    float s0 = acc[mt][nt][half * 2 + 0] - __ldg(&g_cnorm[code]);
                    float s1 = acc[mt][nt][half * 2 + 1] - __ldg(&g_cnorm[code + 1]);
                    if (s0 > v) { v = s0; vi = code; }
                    if (s1 > v) { v = s1; vi = code + 1; }
                }
                best[slot] = v; bidx[slot] = vi;
            }
        }
    }

    // reduce across quad lanes (columns), then across wn warps
    #pragma unroll
    for (int slot = 0; slot < 8; slot++) {
        float v = best[slot];
        int   vi = bidx[slot];
        #pragma unroll
        for (int off = 1; off <= 2; off <<= 1) {
            float ov = __shfl_xor_sync(0xffffffffu, v, off);
            int   oi = __shfl_xor_sync(0xffffffffu, vi, off);
            if (ov > v || (ov == v && oi < vi)) { v = ov; vi = oi; }
        }
        if (tq == 0) {
            int mt = slot >> 1, half = slot & 1;
            int row = wm * 64 + mt * 16 + half * 8 + g;
            *(float*)(smem + SM_EB + (row * 4 + wn) * 4) = v;
            *(int*)(smem + SM_EI + (row * 4 + wn) * 4)   = vi;
        }
    }
    __syncthreads();
    if (tid < 128) {
        float v = -3.0e38f;
        int   vi = 0;
        #pragma unroll
        for (int w = 0; w < 4; w++) {
            float ov = *(float*)(smem + SM_EB + (tid * 4 + w) * 4);
            int   oi = *(int*)(smem + SM_EI + (tid * 4 + w) * 4);
            if (ov > v || (ov == v && oi < vi)) { v = ov; vi = oi; }
        }
        g_idx[t0 + tid] = vi;
        atomicAdd(&g_cnt[vi], 1);   // fused histogram
    }
}

// ---------------- kernel 3: prefix scan + EMA cluster size -------------------
__global__ void __launch_bounds__(1024) scan_csize_kernel(const float* __restrict__ ema_cs) {
    __shared__ int sc[1024];
    __shared__ float red[32];
    int k = threadIdx.x;
    int c = g_cnt[k];
    sc[k] = c;
    __syncthreads();
    #pragma unroll
    for (int off = 1; off < 1024; off <<= 1) {
        int v = (k >= off) ? sc[k - off] : 0;
        __syncthreads();
        sc[k] += v;
        __syncthreads();
    }
    int start = sc[k] - c;
    g_segstart[k] = start;
    g_cursor[k]   = start;

    float cs = 0.99f * ema_cs[k] + 0.01f * (float)c;
    float s = cs;
    #pragma unroll
    for (int o = 16; o; o >>= 1) s += __shfl_xor_sync(0xffffffffu, s, o);
    if ((k & 31) == 0) red[k >> 5] = s;
    __syncthreads();
    if (k < 32) {
        float t = red[k];
        #pragma unroll
        for (int o = 16; o; o >>= 1) t += __shfl_xor_sync(0xffffffffu, t, o);
        if (k == 0) red[0] = t;
    }
    __syncthreads();
    float n = red[0];
    g_csize[k] = (cs + 1e-5f) / (n + K_CODES * 1e-5f) * n;
}

// ---------------- kernel 4: cursor scatter (sorted token list) ---------------
__global__ void __launch_bounds__(256) sort_kernel() {
    int t = blockIdx.x * 256 + threadIdx.x;
    int kk = g_idx[t];
    int pos = atomicAdd(&g_cursor[kk], 1);
    g_sorted[pos] = t;
}

// ---------------- kernel 5: segment sum + updated codebook (fused) -----------
__global__ void __launch_bounds__(256) sum_newembed_kernel(const float* __restrict__ ema_es) {
    int k = blockIdx.x, d = threadIdx.x;
    int start = g_segstart[k], cnt = g_cnt[k];
    const int* srt = g_sorted + start;
    float acc = 0.f;
    int i = 0;
    for (; i + 4 <= cnt; i += 4) {
        int a0 = srt[i], a1 = srt[i + 1], a2 = srt[i + 2], a3 = srt[i + 3];
        float v0 = __ldg(&g_Zt[(size_t)a0 * DIMS + d]);
        float v1 = __ldg(&g_Zt[(size_t)a1 * DIMS + d]);
        float v2 = __ldg(&g_Zt[(size_t)a2 * DIMS + d]);
        float v3 = __ldg(&g_Zt[(size_t)a3 * DIMS + d]);
        acc += v0 + v1 + v2 + v3;
    }
    for (; i < cnt; i++)
        acc += __ldg(&g_Zt[(size_t)srt[i] * DIMS + d]);

    size_t o = (size_t)k * DIMS + d;
    g_newembed[o] = (0.99f * ema_es[o] + 0.01f * acc) / g_csize[k];
}

// ---------------- kernel 6: gather z_q, loss partial, indices ----------------
__global__ void __launch_bounds__(256) gather_kernel(const float* __restrict__ z,
                                                     float* __restrict__ out) {
    int t = blockIdx.x * 256 + threadIdx.x;
    int b = t >> 14;
    int s = t & (SPATIAL - 1);
    int kk = g_idx[t];
    const float* zp = z + (size_t)b * DIMS * SPATIAL + s;
    float*       op = out + (size_t)b * DIMS * SPATIAL + s;
    const float* er = g_newembed + (size_t)kk * DIMS;

    float acc = 0.f;
    #pragma unroll 4
    for (int c = 0; c < DIMS; c++) {
        float zv = zp[(size_t)c * SPATIAL];
        float e  = __ldg(&er[c]);
        float d2 = zv - e;
        acc += d2 * d2;
        op[(size_t)c * SPATIAL] = zv + (e - zv);
    }
    out[(size_t)NZ + 1 + t] = (float)kk;

    #pragma unroll
    for (int o = 16; o; o >>= 1) acc += __shfl_xor_sync(0xffffffffu, acc, o);
    __shared__ float red[8];
    if ((threadIdx.x & 31) == 0) red[threadIdx.x >> 5] = acc;
    __syncthreads();
    if (threadIdx.x == 0) {
        float tt = 0.f;
        #pragma unroll
        for (int i = 0; i < 8; i++) tt += red[i];
        atomicAdd(&g_sq, tt);
    }
}

// ---------------- kernel 7: final loss ---------------------------------------
__global__ void loss_kernel(float* __restrict__ out) {
    out[NZ] = 0.25f * g_sq / (float)NZ;
}

// ---------------- launch -----------------------------------------------------
extern "C" void kernel_launch(void* const* d_in, const int* in_sizes, int n_in,
                              void* d_out, int out_size) {
    (void)in_sizes; (void)n_in; (void)out_size;
    const float* z      = (const float*)d_in[0];
    const float* embed  = (const float*)d_in[1];
    const float* ema_cs = (const float*)d_in[2];
    const float* ema_es = (const float*)d_in[3];
    float* out = (float*)d_out;

    static int smem_set = 0;
    if (!smem_set) {
        cudaFuncSetAttribute(mma_argmax_kernel,
                             cudaFuncAttributeMaxDynamicSharedMemorySize, GEMM_SMEM);
        smem_set = 1;
    }

    prep_embed_kernel<<<K_CODES, 256>>>(embed);
    prep_z_kernel<<<NTOK / 32, 256>>>(z);
    mma_argmax_kernel<<<NTOK / 128, 256, GEMM_SMEM>>>();
    scan_csize_kernel<<<1, 1024>>>(ema_cs);
    sort_kernel<<<NTOK / 256, 256>>>();
    sum_newembed_kernel<<<K_CODES, 256>>>(ema_es);
    gather_kernel<<<NTOK / 256, 256>>>(z, out);
    loss_kernel<<<1, 1>>>(out);
}